// round 1
// baseline (speedup 1.0000x reference)
#include <cuda_runtime.h>
#include <math.h>

// Problem constants
#define DT 0.01f
#define N_STEPS 20

// Fused weights computed once per launch by prep kernel
__device__ float g_Wqe[60 * 64];  // query_w @ ro_w1[88:152]  (60x64)
__device__ float g_c[64];         // ro_b1 + sum(ro_w1[0:24]) + query_b @ ro_w1[88:152]

__global__ void prep_kernel(const float* __restrict__ qw,   // (60,64)
                            const float* __restrict__ qb,   // (64,)
                            const float* __restrict__ w1,   // (152,64)
                            const float* __restrict__ b1)   // (64,)
{
    int tid = threadIdx.x;  // 256 threads
    for (int idx = tid; idx < 60 * 64; idx += 256) {
        int i = idx >> 6;
        int k = idx & 63;
        float acc = 0.0f;
#pragma unroll 8
        for (int m = 0; m < 64; m++)
            acc = fmaf(qw[i * 64 + m], w1[(88 + m) * 64 + k], acc);
        g_Wqe[idx] = acc;
    }
    if (tid < 64) {
        int k = tid;
        float acc = b1[k];
        // rows 0..23 of combined are identically 1.0 (delta/theta amplitudes)
        for (int r = 0; r < 24; r++) acc += w1[r * 64 + k];
        // fold query bias through the readout
        for (int m = 0; m < 64; m++)
            acc = fmaf(qb[m], w1[(88 + m) * 64 + k], acc);
        g_c[k] = acc;
    }
}

// Shared layout (floats):
//  sWsT  [64*16]  : scene_w transposed, sWsT[j*16+d] = scene_w[d*64+j]
//  sWg   [64*64]  : ro_w1 rows 24..87
//  sWqe  [60*64]
//  sc    [64]
//  sbs   [64]     : scene_b
//  sw2   [128]    : ro_w2 (64,2)
//  sb2   [4]      : ro_b2 (padded)
//  sQ    [128*61] : staged query, padded stride 61 (conflict-free)
#define OFF_WST 0
#define OFF_WG 1024
#define OFF_WQE 5120
#define OFF_C 8960
#define OFF_BS 9024
#define OFF_W2 9088
#define OFF_B2 9216
#define OFF_Q 9220
#define SMEM_FLOATS (OFF_Q + 128 * 61)
#define SMEM_BYTES (SMEM_FLOATS * 4)

__global__ __launch_bounds__(128, 3) void dtg_kernel(
    const float* __restrict__ scene,    // (B,8,16)
    const float* __restrict__ query,    // (B,60)
    const float* __restrict__ scene_w,  // (16,64)
    const float* __restrict__ scene_b,  // (64,)
    const float* __restrict__ w1,       // (152,64)
    const float* __restrict__ w2,       // (64,2)
    const float* __restrict__ b2,       // (2,)
    float* __restrict__ out,            // (B,2)
    int B)
{
    extern __shared__ float smem[];
    float* sWsT = smem + OFF_WST;
    float* sWg = smem + OFF_WG;
    float* sWqe = smem + OFF_WQE;
    float* sc = smem + OFF_C;
    float* sbs = smem + OFF_BS;
    float* sw2 = smem + OFF_W2;
    float* sb2 = smem + OFF_B2;
    float* sQ = smem + OFF_Q;

    const int tid = threadIdx.x;

    // ---- cooperative weight loads ----
    for (int idx = tid; idx < 16 * 64; idx += 128) {
        int d = idx >> 6, k = idx & 63;
        sWsT[k * 16 + d] = scene_w[idx];
    }
    for (int idx = tid; idx < 64 * 64; idx += 128)
        sWg[idx] = w1[24 * 64 + idx];
    for (int idx = tid; idx < 60 * 64; idx += 128)
        sWqe[idx] = g_Wqe[idx];
    if (tid < 64) {
        sc[tid] = g_c[tid];
        sbs[tid] = scene_b[tid];
    }
    if (tid < 128) sw2[tid] = w2[tid];
    if (tid < 2) sb2[tid] = b2[tid];

    // ---- stage this block's query rows into shared (padded stride 61) ----
    {
        int s0 = blockIdx.x * 128;
        int nt = B - s0;
        if (nt > 128) nt = 128;
        if (nt > 0) {
            const float4* qg = (const float4*)(query + (size_t)s0 * 60);
            int limit4 = nt * 15;  // 60/4 float4 per sample
            for (int g = tid; g < limit4; g += 128) {
                float4 v = qg[g];
                int r = g / 15;
                int cpos = g - r * 15;
                float* dst = sQ + r * 61 + cpos * 4;
                dst[0] = v.x;
                dst[1] = v.y;
                dst[2] = v.z;
                dst[3] = v.w;
            }
        }
    }
    __syncthreads();

    const int s = blockIdx.x * 128 + tid;
    if (s >= B) return;

    // ---- init h with fused bias ----
    float h[64];
#pragma unroll
    for (int k4 = 0; k4 < 16; k4++) {
        float4 cc = ((const float4*)sc)[k4];
        h[4 * k4 + 0] = cc.x;
        h[4 * k4 + 1] = cc.y;
        h[4 * k4 + 2] = cc.z;
        h[4 * k4 + 3] = cc.w;
    }

    // ---- query path: h += q @ Wqe ----
    {
        const float* qr = sQ + tid * 61;
#pragma unroll 4
        for (int i = 0; i < 60; i++) {
            float qi = qr[i];
            const float4* wrow = (const float4*)(sWqe + i * 64);
#pragma unroll
            for (int k4 = 0; k4 < 16; k4++) {
                float4 w = wrow[k4];
                h[4 * k4 + 0] = fmaf(qi, w.x, h[4 * k4 + 0]);
                h[4 * k4 + 1] = fmaf(qi, w.y, h[4 * k4 + 1]);
                h[4 * k4 + 2] = fmaf(qi, w.z, h[4 * k4 + 2]);
                h[4 * k4 + 3] = fmaf(qi, w.w, h[4 * k4 + 3]);
            }
        }
    }

    // ---- scene mean over the 8 objects -> s16[16] ----
    float s16[16];
    {
        const float4* sp = (const float4*)(scene + (size_t)s * 128);
        float4 a0 = sp[0], a1 = sp[1], a2 = sp[2], a3 = sp[3];
#pragma unroll
        for (int n = 1; n < 8; n++) {
            float4 v0 = sp[n * 4 + 0], v1 = sp[n * 4 + 1];
            float4 v2 = sp[n * 4 + 2], v3 = sp[n * 4 + 3];
            a0.x += v0.x; a0.y += v0.y; a0.z += v0.z; a0.w += v0.w;
            a1.x += v1.x; a1.y += v1.y; a1.z += v1.z; a1.w += v1.w;
            a2.x += v2.x; a2.y += v2.y; a2.z += v2.z; a2.w += v2.w;
            a3.x += v3.x; a3.y += v3.y; a3.z += v3.z; a3.w += v3.w;
        }
        const float inv8 = 0.125f;
        s16[0] = a0.x * inv8;  s16[1] = a0.y * inv8;
        s16[2] = a0.z * inv8;  s16[3] = a0.w * inv8;
        s16[4] = a1.x * inv8;  s16[5] = a1.y * inv8;
        s16[6] = a1.z * inv8;  s16[7] = a1.w * inv8;
        s16[8] = a2.x * inv8;  s16[9] = a2.y * inv8;
        s16[10] = a2.z * inv8; s16[11] = a2.w * inv8;
        s16[12] = a3.x * inv8; s16[13] = a3.y * inv8;
        s16[14] = a3.z * inv8; s16[15] = a3.w * inv8;
    }

    // ---- gamma path: for each j, compute ag_j and accumulate into h ----
#pragma unroll 1
    for (int j0 = 0; j0 < 64; j0 += 4) {
        float a[4];
#pragma unroll
        for (int u = 0; u < 4; u++) {
            int j = j0 + u;
            const float4* wst = (const float4*)(sWsT + j * 16);
            float4 w0 = wst[0], w1v = wst[1], w2v = wst[2], w3v = wst[3];
            float p = sbs[j];
            p = fmaf(s16[0], w0.x, p);  p = fmaf(s16[1], w0.y, p);
            p = fmaf(s16[2], w0.z, p);  p = fmaf(s16[3], w0.w, p);
            p = fmaf(s16[4], w1v.x, p); p = fmaf(s16[5], w1v.y, p);
            p = fmaf(s16[6], w1v.z, p); p = fmaf(s16[7], w1v.w, p);
            p = fmaf(s16[8], w2v.x, p); p = fmaf(s16[9], w2v.y, p);
            p = fmaf(s16[10], w2v.z, p); p = fmaf(s16[11], w2v.w, p);
            p = fmaf(s16[12], w3v.x, p); p = fmaf(s16[13], w3v.y, p);
            p = fmaf(s16[14], w3v.z, p); p = fmaf(s16[15], w3v.w, p);
            // sigmoid
            a[u] = 1.0f / (1.0f + __expf(-p));
        }
        // 20 Euler steps of a' = a(1-a^2) (phase-independent; ad/at stay 1)
#pragma unroll
        for (int t = 0; t < N_STEPS; t++) {
#pragma unroll
            for (int u = 0; u < 4; u++) {
                float aa = a[u] * a[u];
                float da = fmaf(-aa, a[u], a[u]);  // a - a^3 = a(1-a^2)
                a[u] = fmaf(DT, da, a[u]);
            }
        }
        // h += ag_j * Wg[j][:]
#pragma unroll
        for (int u = 0; u < 4; u++) {
            int j = j0 + u;
            const float4* wg = (const float4*)(sWg + j * 64);
            float aj = a[u];
#pragma unroll
            for (int k4 = 0; k4 < 16; k4++) {
                float4 w = wg[k4];
                h[4 * k4 + 0] = fmaf(aj, w.x, h[4 * k4 + 0]);
                h[4 * k4 + 1] = fmaf(aj, w.y, h[4 * k4 + 1]);
                h[4 * k4 + 2] = fmaf(aj, w.z, h[4 * k4 + 2]);
                h[4 * k4 + 3] = fmaf(aj, w.w, h[4 * k4 + 3]);
            }
        }
    }

    // ---- readout: relu, 64->2, log_softmax ----
    float l0 = sb2[0], l1 = sb2[1];
#pragma unroll
    for (int k = 0; k < 64; k++) {
        float hk = fmaxf(h[k], 0.0f);
        float2 w = ((const float2*)sw2)[k];
        l0 = fmaf(hk, w.x, l0);
        l1 = fmaf(hk, w.y, l1);
    }
    float mx = fmaxf(l0, l1);
    float lse = mx + log1pf(__expf(-fabsf(l0 - l1)));
    ((float2*)out)[s] = make_float2(l0 - lse, l1 - lse);
}

extern "C" void kernel_launch(void* const* d_in, const int* in_sizes, int n_in,
                              void* d_out, int out_size) {
    const float* scene = (const float*)d_in[0];    // (B,8,16)
    const float* query = (const float*)d_in[1];    // (B,60)
    // d_in[2..7]: phases/freqs — provably unused (amplitude ODE is phase-free,
    // delta/theta amplitudes stay at the fixed point 1.0)
    const float* scene_w = (const float*)d_in[8];  // (16,64)
    const float* scene_b = (const float*)d_in[9];  // (64,)
    const float* query_w = (const float*)d_in[10]; // (60,64)
    const float* query_b = (const float*)d_in[11]; // (64,)
    const float* ro_w1 = (const float*)d_in[12];   // (152,64)
    const float* ro_b1 = (const float*)d_in[13];   // (64,)
    const float* ro_w2 = (const float*)d_in[14];   // (64,2)
    const float* ro_b2 = (const float*)d_in[15];   // (2,)
    float* out = (float*)d_out;

    int B = in_sizes[0] / 128;  // scene has 8*16 floats per sample

    static bool attr_set = false;
    if (!attr_set) {
        cudaFuncSetAttribute(dtg_kernel, cudaFuncAttributeMaxDynamicSharedMemorySize,
                             SMEM_BYTES);
        attr_set = true;
    }

    prep_kernel<<<1, 256>>>(query_w, query_b, ro_w1, ro_b1);
    int grid = (B + 127) / 128;
    dtg_kernel<<<grid, 128, SMEM_BYTES>>>(scene, query, scene_w, scene_b, ro_w1,
                                          ro_w2, ro_b2, out, B);
}

// round 2
// speedup vs baseline: 1.3410x; 1.3410x over previous
#include <cuda_runtime.h>
#include <math.h>

#define DT 0.01f
#define N_STEPS 20
#define PMIN (-8.0f)
#define TAB_N 1024
#define TAB_STEP (16.0f / (float)TAB_N)
#define TAB_INV_STEP ((float)TAB_N / 16.0f)

// Precomputed by prep kernel
__device__ float g_Wqe[60 * 64];   // query_w @ ro_w1[88:152]
__device__ float g_c[64];          // ro_b1 + sum(ro_w1[0:24]) + query_b @ ro_w1[88:152]
__device__ float2 g_tab[TAB_N];    // {value, delta} table of p -> F20(sigmoid(p))

__global__ void prep_kernel(const float* __restrict__ qw,   // (60,64)
                            const float* __restrict__ qb,   // (64,)
                            const float* __restrict__ w1,   // (152,64)
                            const float* __restrict__ b1)   // (64,)
{
    int bid = blockIdx.x, tid = threadIdx.x;
    if (bid < 15) {
        // g_Wqe: 3840 elements, 256 per block
        int idx = bid * 256 + tid;
        int i = idx >> 6, k = idx & 63;
        float acc = 0.0f;
#pragma unroll 8
        for (int m = 0; m < 64; m++)
            acc = fmaf(qw[i * 64 + m], w1[(88 + m) * 64 + k], acc);
        g_Wqe[idx] = acc;
    } else if (bid == 15) {
        if (tid < 64) {
            int k = tid;
            float acc = b1[k];
            for (int r = 0; r < 24; r++) acc += w1[r * 64 + k];  // delta/theta amps == 1
            for (int m = 0; m < 64; m++)
                acc = fmaf(qb[m], w1[(88 + m) * 64 + k], acc);
            g_c[k] = acc;
        }
    } else {
        // amplitude-evolution lookup table
        __shared__ float v[TAB_N + 1];
        for (int i = tid; i <= TAB_N; i += 256) {
            float p = PMIN + (float)i * TAB_STEP;
            float a = 1.0f / (1.0f + expf(-p));
#pragma unroll
            for (int t = 0; t < N_STEPS; t++) {
                float t2 = 1.0f - a * a;
                a = fmaf(DT, a * t2, a);
            }
            v[i] = a;
        }
        __syncthreads();
        for (int i = tid; i < TAB_N; i += 256)
            g_tab[i] = make_float2(v[i], v[i + 1] - v[i]);
    }
}

// ---- packed fp32x2 helpers ----
typedef unsigned long long u64t;
__device__ __forceinline__ u64t pack2(float lo, float hi) {
    u64t r;
    asm("mov.b64 %0, {%1, %2};" : "=l"(r) : "f"(lo), "f"(hi));
    return r;
}
__device__ __forceinline__ void unpack2(u64t v, float& lo, float& hi) {
    asm("mov.b64 {%0, %1}, %2;" : "=f"(lo), "=f"(hi) : "l"(v));
}
__device__ __forceinline__ void ffma2(u64t& d, u64t a, u64t b) {
    asm("fma.rn.f32x2 %0, %1, %2, %0;" : "+l"(d) : "l"(a), "l"(b));
}
__device__ __forceinline__ u64t mul2(u64t a, u64t b) {
    u64t r;
    asm("mul.rn.f32x2 %0, %1, %2;" : "=l"(r) : "l"(a), "l"(b));
    return r;
}

// Shared layout (floats)
#define OFF_TAB 0                 // 1024 float2 = 2048 floats
#define OFF_WG 2048               // 64x64
#define OFF_WQE 6144              // 60x64
#define OFF_WST 9984              // 64x16 (scene_w transposed [j][d])
#define OFF_BS 11008              // 64
#define OFF_C 11072               // 64
#define OFF_W2 11136              // 128
#define OFF_B2 11264              // 4 (padded)
#define OFF_Q 11280               // 128 x 17 (query chunk, padded stride)
#define SMEM_FLOATS (OFF_Q + 128 * 17)
#define SMEM_BYTES (SMEM_FLOATS * 4)

__global__ __launch_bounds__(128, 4) void dtg_kernel(
    const float* __restrict__ scene,    // (B,8,16)
    const float* __restrict__ query,    // (B,60)
    const float* __restrict__ scene_w,  // (16,64)
    const float* __restrict__ scene_b,  // (64,)
    const float* __restrict__ w1,       // (152,64)
    const float* __restrict__ w2,       // (64,2)
    const float* __restrict__ b2,       // (2,)
    float* __restrict__ out,            // (B,2)
    int B)
{
    extern __shared__ float smem[];
    float* sTab = smem + OFF_TAB;
    float* sWg = smem + OFF_WG;
    float* sWqe = smem + OFF_WQE;
    float* sWsT = smem + OFF_WST;
    float* sbs = smem + OFF_BS;
    float* sc = smem + OFF_C;
    float* sw2 = smem + OFF_W2;
    float* sb2 = smem + OFF_B2;
    float* sQ = smem + OFF_Q;

    const int tid = threadIdx.x;
    const int s0 = blockIdx.x * 128;
    const int s = s0 + tid;
    const bool valid = (s < B);
    int nt = B - s0;
    if (nt > 128) nt = 128;
    if (nt < 0) nt = 0;

    // ---- cooperative loads: table + weights ----
    {
        const float4* tg = (const float4*)g_tab;
        float4* ts = (float4*)sTab;
        for (int i = tid; i < 512; i += 128) ts[i] = tg[i];
    }
    for (int idx = tid; idx < 64 * 64; idx += 128)
        sWg[idx] = w1[24 * 64 + idx];
    for (int idx = tid; idx < 60 * 64; idx += 128)
        sWqe[idx] = g_Wqe[idx];
    for (int idx = tid; idx < 16 * 64; idx += 128) {
        int d = idx >> 6, k = idx & 63;
        sWsT[k * 16 + d] = scene_w[idx];
    }
    if (tid < 64) {
        sbs[tid] = scene_b[tid];
        sc[tid] = g_c[tid];
    }
    if (tid < 128) sw2[tid] = w2[tid];
    if (tid < 2) sb2[tid] = b2[tid];

    // stage query chunk 0 (cols 0..14)
    for (int g = tid; g < nt * 15; g += 128) {
        int r = g / 15, ii = g - r * 15;
        sQ[r * 17 + ii] = query[(size_t)(s0 + r) * 60 + ii];
    }
    __syncthreads();

    // ---- scene mean -> packed s2[8] (16 values) ----
    u64t s2[8];
    {
        float4 a0 = make_float4(0.f, 0.f, 0.f, 0.f), a1 = a0, a2 = a0, a3 = a0;
        if (valid) {
            const float4* sp = (const float4*)(scene + (size_t)s * 128);
            a0 = sp[0]; a1 = sp[1]; a2 = sp[2]; a3 = sp[3];
#pragma unroll
            for (int n = 1; n < 8; n++) {
                float4 v0 = sp[n * 4 + 0], v1 = sp[n * 4 + 1];
                float4 v2 = sp[n * 4 + 2], v3 = sp[n * 4 + 3];
                a0.x += v0.x; a0.y += v0.y; a0.z += v0.z; a0.w += v0.w;
                a1.x += v1.x; a1.y += v1.y; a1.z += v1.z; a1.w += v1.w;
                a2.x += v2.x; a2.y += v2.y; a2.z += v2.z; a2.w += v2.w;
                a3.x += v3.x; a3.y += v3.y; a3.z += v3.z; a3.w += v3.w;
            }
        }
        const float q8 = 0.125f;
        s2[0] = pack2(a0.x * q8, a0.y * q8);
        s2[1] = pack2(a0.z * q8, a0.w * q8);
        s2[2] = pack2(a1.x * q8, a1.y * q8);
        s2[3] = pack2(a1.z * q8, a1.w * q8);
        s2[4] = pack2(a2.x * q8, a2.y * q8);
        s2[5] = pack2(a2.z * q8, a2.w * q8);
        s2[6] = pack2(a3.x * q8, a3.y * q8);
        s2[7] = pack2(a3.z * q8, a3.w * q8);
    }

    // ---- init h (packed, 32 x f32x2) with fused bias ----
    u64t h2[32];
    {
        const ulonglong2* cp = (const ulonglong2*)sc;
#pragma unroll
        for (int k4 = 0; k4 < 16; k4++) {
            ulonglong2 c = cp[k4];
            h2[2 * k4 + 0] = c.x;
            h2[2 * k4 + 1] = c.y;
        }
    }

    // ---- gamma path: p_j -> table lookup -> h += ag_j * Wg[j] ----
#pragma unroll 2
    for (int j = 0; j < 64; j++) {
        const ulonglong2* wst = (const ulonglong2*)(sWsT + j * 16);
        ulonglong2 wa = wst[0], wb = wst[1], wc = wst[2], wd = wst[3];
        u64t acc = mul2(s2[0], wa.x);
        ffma2(acc, s2[1], wa.y);
        ffma2(acc, s2[2], wb.x);
        ffma2(acc, s2[3], wb.y);
        ffma2(acc, s2[4], wc.x);
        ffma2(acc, s2[5], wc.y);
        ffma2(acc, s2[6], wd.x);
        ffma2(acc, s2[7], wd.y);
        float plo, phi;
        unpack2(acc, plo, phi);
        float p = plo + phi + sbs[j];
        // table lookup with linear interpolation
        float xf = (p - PMIN) * TAB_INV_STEP;
        int ix = __float2int_rd(xf);
        ix = min(max(ix, 0), TAB_N - 1);
        float fr = xf - (float)ix;
        float2 tv = ((const float2*)sTab)[ix];
        float ag = fmaf(fr, tv.y, tv.x);

        u64t a2v = pack2(ag, ag);
        const ulonglong2* wg = (const ulonglong2*)(sWg + j * 64);
#pragma unroll
        for (int k4 = 0; k4 < 16; k4++) {
            ulonglong2 w = wg[k4];
            ffma2(h2[2 * k4 + 0], a2v, w.x);
            ffma2(h2[2 * k4 + 1], a2v, w.y);
        }
    }

    // ---- query path in 4 chunks of 15 ----
#pragma unroll 1
    for (int c = 0; c < 4; c++) {
        if (c > 0) {
            __syncthreads();
            int base = c * 15;
            for (int g = tid; g < nt * 15; g += 128) {
                int r = g / 15, ii = g - r * 15;
                sQ[r * 17 + ii] = query[(size_t)(s0 + r) * 60 + base + ii];
            }
            __syncthreads();
        }
#pragma unroll 3
        for (int ii = 0; ii < 15; ii++) {
            float qi = sQ[tid * 17 + ii];
            u64t q2 = pack2(qi, qi);
            const ulonglong2* wrow = (const ulonglong2*)(sWqe + (c * 15 + ii) * 64);
#pragma unroll
            for (int k4 = 0; k4 < 16; k4++) {
                ulonglong2 w = wrow[k4];
                ffma2(h2[2 * k4 + 0], q2, w.x);
                ffma2(h2[2 * k4 + 1], q2, w.y);
            }
        }
    }

    // ---- readout: relu, 64->2, log_softmax ----
    if (!valid) return;
    float l0 = sb2[0], l1 = sb2[1];
#pragma unroll
    for (int k2 = 0; k2 < 32; k2++) {
        float ha, hb;
        unpack2(h2[k2], ha, hb);
        ha = fmaxf(ha, 0.0f);
        hb = fmaxf(hb, 0.0f);
        float2 wa = ((const float2*)sw2)[2 * k2 + 0];
        float2 wb = ((const float2*)sw2)[2 * k2 + 1];
        l0 = fmaf(ha, wa.x, l0);
        l1 = fmaf(ha, wa.y, l1);
        l0 = fmaf(hb, wb.x, l0);
        l1 = fmaf(hb, wb.y, l1);
    }
    float mx = fmaxf(l0, l1);
    float lse = mx + log1pf(__expf(-fabsf(l0 - l1)));
    ((float2*)out)[s] = make_float2(l0 - lse, l1 - lse);
}

extern "C" void kernel_launch(void* const* d_in, const int* in_sizes, int n_in,
                              void* d_out, int out_size) {
    const float* scene = (const float*)d_in[0];    // (B,8,16)
    const float* query = (const float*)d_in[1];    // (B,60)
    // d_in[2..7]: phases/freqs — unused (amplitude ODE is phase-free; delta/theta
    // amplitudes start at the fixed point 1.0 and stay there)
    const float* scene_w = (const float*)d_in[8];  // (16,64)
    const float* scene_b = (const float*)d_in[9];  // (64,)
    const float* query_w = (const float*)d_in[10]; // (60,64)
    const float* query_b = (const float*)d_in[11]; // (64,)
    const float* ro_w1 = (const float*)d_in[12];   // (152,64)
    const float* ro_b1 = (const float*)d_in[13];   // (64,)
    const float* ro_w2 = (const float*)d_in[14];   // (64,2)
    const float* ro_b2 = (const float*)d_in[15];   // (2,)
    float* out = (float*)d_out;

    int B = in_sizes[0] / 128;

    static bool attr_set = false;
    if (!attr_set) {
        cudaFuncSetAttribute(dtg_kernel, cudaFuncAttributeMaxDynamicSharedMemorySize,
                             SMEM_BYTES);
        attr_set = true;
    }

    prep_kernel<<<17, 256>>>(query_w, query_b, ro_w1, ro_b1);
    int grid = (B + 127) / 128;
    dtg_kernel<<<grid, 128, SMEM_BYTES>>>(scene, query, scene_w, scene_b, ro_w1,
                                          ro_w2, ro_b2, out, B);
}

// round 4
// speedup vs baseline: 2.0970x; 1.5638x over previous
#include <cuda_runtime.h>
#include <cuda_bf16.h>
#include <math.h>
#include <stdint.h>

#define DT 0.01f
#define N_STEPS 20
#define PMIN (-8.0f)
#define TAB_N 1024
#define TAB_STEP (16.0f / (float)TAB_N)
#define TAB_INV_STEP ((float)TAB_N / 16.0f)

// ---------------- precomputed globals ----------------
__device__ __align__(16) float g_Wqe[60 * 64];    // query_w @ ro_w1[88:152]
__device__ __align__(16) float g_c[64];           // fused bias
__device__ __align__(16) float2 g_tab[TAB_N];     // p -> F20(sigmoid(p))
__device__ __align__(16) float g_WsT[64 * 16];    // scene_w transposed [j][d]
// B operand fragments (m16n8k16 layout), bf16 hi/lo split, frag-linear:
// idx = ((kt*8+nt)*32+lane)*2+reg
__device__ __align__(16) uint32_t g_Bhi[4096];
__device__ __align__(16) uint32_t g_Blo[4096];

// ---------------- helpers ----------------
typedef unsigned long long u64t;
__device__ __forceinline__ u64t pack2(float lo, float hi) {
    u64t r;
    asm("mov.b64 %0, {%1, %2};" : "=l"(r) : "f"(lo), "f"(hi));
    return r;
}
__device__ __forceinline__ void unpack2(u64t v, float& lo, float& hi) {
    asm("mov.b64 {%0, %1}, %2;" : "=f"(lo), "=f"(hi) : "l"(v));
}
__device__ __forceinline__ void ffma2(u64t& d, u64t a, u64t b) {
    asm("fma.rn.f32x2 %0, %1, %2, %0;" : "+l"(d) : "l"(a), "l"(b));
}
__device__ __forceinline__ u64t mul2(u64t a, u64t b) {
    u64t r;
    asm("mul.rn.f32x2 %0, %1, %2;" : "=l"(r) : "l"(a), "l"(b));
    return r;
}

// split (v0,v1) into bf16x2 hi and bf16x2 lo packed words (low half = v0)
__device__ __forceinline__ void split2(float v0, float v1, uint32_t& hi, uint32_t& lo) {
    __nv_bfloat16 h0 = __float2bfloat16(v0);
    __nv_bfloat16 h1 = __float2bfloat16(v1);
    float r0 = v0 - __bfloat162float(h0);
    float r1 = v1 - __bfloat162float(h1);
    __nv_bfloat16 l0 = __float2bfloat16(r0);
    __nv_bfloat16 l1 = __float2bfloat16(r1);
    hi = ((uint32_t)__bfloat16_as_ushort(h1) << 16) | (uint32_t)__bfloat16_as_ushort(h0);
    lo = ((uint32_t)__bfloat16_as_ushort(l1) << 16) | (uint32_t)__bfloat16_as_ushort(l0);
}

// m16n8k16 bf16 MMA, D += A*B (C aliased to D)
__device__ __forceinline__ void mma16816(float* d, const uint32_t* a, const uint32_t* b) {
    asm("mma.sync.aligned.m16n8k16.row.col.f32.bf16.bf16.f32 "
        "{%0,%1,%2,%3}, {%4,%5,%6,%7}, {%8,%9}, {%0,%1,%2,%3};"
        : "+f"(d[0]), "+f"(d[1]), "+f"(d[2]), "+f"(d[3])
        : "r"(a[0]), "r"(a[1]), "r"(a[2]), "r"(a[3]), "r"(b[0]), "r"(b[1]));
}

// ---------------- prep kernels ----------------
__global__ void prep1_kernel(const float* __restrict__ qw,   // (60,64)
                             const float* __restrict__ qb,   // (64,)
                             const float* __restrict__ w1,   // (152,64)
                             const float* __restrict__ b1,   // (64,)
                             const float* __restrict__ sw)   // scene_w (16,64)
{
    int bid = blockIdx.x, tid = threadIdx.x;
    if (bid < 15) {
        int idx = bid * 256 + tid;
        int i = idx >> 6, k = idx & 63;
        float acc = 0.0f;
#pragma unroll 8
        for (int m = 0; m < 64; m++)
            acc = fmaf(qw[i * 64 + m], w1[(88 + m) * 64 + k], acc);
        g_Wqe[idx] = acc;
    } else if (bid == 15) {
        if (tid < 64) {
            int k = tid;
            float acc = b1[k];
            for (int r = 0; r < 24; r++) acc += w1[r * 64 + k];  // delta/theta amps == 1
            for (int m = 0; m < 64; m++)
                acc = fmaf(qb[m], w1[(88 + m) * 64 + k], acc);
            g_c[k] = acc;
        }
    } else if (bid == 16) {
        __shared__ float v[TAB_N + 1];
        for (int i = tid; i <= TAB_N; i += 256) {
            float p = PMIN + (float)i * TAB_STEP;
            float a = 1.0f / (1.0f + expf(-p));
#pragma unroll
            for (int t = 0; t < N_STEPS; t++) {
                float t2 = 1.0f - a * a;
                a = fmaf(DT, a * t2, a);
            }
            v[i] = a;
        }
        __syncthreads();
        for (int i = tid; i < TAB_N; i += 256)
            g_tab[i] = make_float2(v[i], v[i + 1] - v[i]);
    } else {
        for (int idx = tid; idx < 16 * 64; idx += 256) {
            int d = idx >> 6, j = idx & 63;
            g_WsT[j * 16 + d] = sw[idx];
        }
    }
}

// B rows: k 0..63 = Wg (ro_w1[24+k][n]); 64..123 = Wqe[k-64][n]; 124..127 = 0
__device__ __forceinline__ float fetchB(int k, int n, const float* w1) {
    if (k < 64) return w1[(24 + k) * 64 + n];
    if (k < 124) return g_Wqe[(k - 64) * 64 + n];
    return 0.0f;
}

__global__ void prep2_kernel(const float* __restrict__ w1) {
    int idx = blockIdx.x * 256 + threadIdx.x;  // 0..4095
    int reg = idx & 1;
    int lane = (idx >> 1) & 31;
    int nt = (idx >> 6) & 7;
    int kt = idx >> 9;
    int g = lane >> 2, t = lane & 3;
    int n = nt * 8 + g;
    int k0 = kt * 16 + reg * 8 + 2 * t;
    float v0 = fetchB(k0, n, w1);
    float v1 = fetchB(k0 + 1, n, w1);
    uint32_t hi, lo;
    split2(v0, v1, hi, lo);
    g_Bhi[idx] = hi;
    g_Blo[idx] = lo;
}

// ---------------- main kernel ----------------
// smem offsets in u32 units
#define O_BHI 0
#define O_BLO 4096
#define O_TAB 8192
#define O_WST 10240
#define O_SC 11264
#define O_SBS 11328
#define O_W2 11392
#define O_SB2 11520
#define O_AW 11536
#define AW_PER_WARP 2176
#define SMEM_U32 (O_AW + 4 * AW_PER_WARP)
#define SMEM_BYTES (SMEM_U32 * 4)

__global__ __launch_bounds__(128) void dtg_kernel(
    const float* __restrict__ scene,    // (B,8,16)
    const float* __restrict__ query,    // (B,60)
    const float* __restrict__ scene_b,  // (64,)
    const float* __restrict__ w2,       // (64,2)
    const float* __restrict__ b2,       // (2,)
    float* __restrict__ out,            // (B,2)
    int B)
{
    extern __shared__ float smem[];
    uint32_t* sm32 = (uint32_t*)smem;

    const int tid = threadIdx.x;
    const int lane = tid & 31;
    const int wid = tid >> 5;
    const int fg = lane >> 2;   // frag group (row within 8)
    const int ft = lane & 3;    // frag quad col

    // ---- cooperative smem fill ----
    {
        float4* bdst = (float4*)(sm32 + O_BHI);
        const float4* bh = (const float4*)g_Bhi;
        const float4* bl = (const float4*)g_Blo;
        for (int i = tid; i < 1024; i += 128) {
            bdst[i] = bh[i];
            bdst[1024 + i] = bl[i];
        }
        const float4* tg = (const float4*)g_tab;
        float4* ts = (float4*)(smem + O_TAB);
        for (int i = tid; i < 512; i += 128) ts[i] = tg[i];
        const float4* wg = (const float4*)g_WsT;
        float4* wsd = (float4*)(smem + O_WST);
        for (int i = tid; i < 256; i += 128) wsd[i] = wg[i];
        if (tid < 64) {
            smem[O_SC + tid] = g_c[tid];
            smem[O_SBS + tid] = scene_b[tid];
        }
        if (tid < 128) smem[O_W2 + tid] = w2[tid];
        if (tid < 2) smem[O_SB2 + tid] = b2[tid];
    }
    __syncthreads();

    const float* sWsT = smem + O_WST;
    const float* sbs = smem + O_SBS;
    const float* sTab = smem + O_TAB;
    uint32_t* awp = sm32 + O_AW + wid * AW_PER_WARP;
    const uint32_t* sBhi = sm32 + O_BHI;
    const uint32_t* sBlo = sm32 + O_BLO;

    const int s = blockIdx.x * 128 + wid * 32 + lane;
    const int s_eff = (s < B) ? s : (B - 1);

    // ---- scene mean -> packed s2[8] (issued early; consumed in gamma stage) ----
    u64t s2[8];
    {
        const float4* sp = (const float4*)(scene + (size_t)s_eff * 128);
        float4 a0 = sp[0], a1 = sp[1], a2 = sp[2], a3 = sp[3];
#pragma unroll
        for (int n = 1; n < 8; n++) {
            float4 v0 = sp[n * 4 + 0], v1 = sp[n * 4 + 1];
            float4 v2 = sp[n * 4 + 2], v3 = sp[n * 4 + 3];
            a0.x += v0.x; a0.y += v0.y; a0.z += v0.z; a0.w += v0.w;
            a1.x += v1.x; a1.y += v1.y; a1.z += v1.z; a1.w += v1.w;
            a2.x += v2.x; a2.y += v2.y; a2.z += v2.z; a2.w += v2.w;
            a3.x += v3.x; a3.y += v3.y; a3.z += v3.z; a3.w += v3.w;
        }
        const float q8 = 0.125f;
        s2[0] = pack2(a0.x * q8, a0.y * q8);
        s2[1] = pack2(a0.z * q8, a0.w * q8);
        s2[2] = pack2(a1.x * q8, a1.y * q8);
        s2[3] = pack2(a1.z * q8, a1.w * q8);
        s2[4] = pack2(a2.x * q8, a2.y * q8);
        s2[5] = pack2(a2.z * q8, a2.w * q8);
        s2[6] = pack2(a3.x * q8, a3.y * q8);
        s2[7] = pack2(a3.z * q8, a3.w * q8);
    }

    // ---- stage 1 first: QUERY activations (k-tiles 4..7), data ready via LDG ----
    {
        float q[64];
        const float4* qg = (const float4*)(query + (size_t)s_eff * 60);
#pragma unroll
        for (int i = 0; i < 15; i++) {
            float4 v = qg[i];
            q[4 * i + 0] = v.x;
            q[4 * i + 1] = v.y;
            q[4 * i + 2] = v.z;
            q[4 * i + 3] = v.w;
        }
        q[60] = q[61] = q[62] = q[63] = 0.0f;
#pragma unroll
        for (int c = 0; c < 32; c++) {
            uint32_t hi, lo;
            split2(q[2 * c], q[2 * c + 1], hi, lo);
            awp[lane * 33 + c] = hi;
            awp[1056 + lane * 33 + c] = lo;
        }
    }
    __syncwarp();

    float d[2][8][4];
#pragma unroll
    for (int mt = 0; mt < 2; mt++)
#pragma unroll
        for (int nt = 0; nt < 8; nt++)
#pragma unroll
            for (int e = 0; e < 4; e++) d[mt][nt][e] = 0.0f;

    // ---- MMA over k-tiles: 4..7 (query, staged), then restage gamma, 0..3 ----
#pragma unroll 1
    for (int half = 0; half < 2; half++) {
        if (half == 1) {
            // restage with GAMMA activations (k-tiles 0..3)
            __syncwarp();
#pragma unroll 2
            for (int c = 0; c < 32; c++) {
                float ag01[2];
#pragma unroll
                for (int u = 0; u < 2; u++) {
                    int j = 2 * c + u;
                    const ulonglong2* wst = (const ulonglong2*)(sWsT + j * 16);
                    ulonglong2 wa = wst[0], wb = wst[1];
                    u64t acc = mul2(s2[0], wa.x);
                    ffma2(acc, s2[1], wa.y);
                    ffma2(acc, s2[2], wb.x);
                    ffma2(acc, s2[3], wb.y);
                    ulonglong2 wc = wst[2], wd = wst[3];
                    ffma2(acc, s2[4], wc.x);
                    ffma2(acc, s2[5], wc.y);
                    ffma2(acc, s2[6], wd.x);
                    ffma2(acc, s2[7], wd.y);
                    float plo, phi;
                    unpack2(acc, plo, phi);
                    float p = plo + phi + sbs[j];
                    float xf = (p - PMIN) * TAB_INV_STEP;
                    int ix = __float2int_rd(xf);
                    ix = min(max(ix, 0), TAB_N - 1);
                    float fr = xf - (float)ix;
                    float2 tv = ((const float2*)sTab)[ix];
                    ag01[u] = fmaf(fr, tv.y, tv.x);
                }
                uint32_t hi, lo;
                split2(ag01[0], ag01[1], hi, lo);
                awp[lane * 33 + c] = hi;
                awp[1056 + lane * 33 + c] = lo;
            }
            __syncwarp();
        }
#pragma unroll
        for (int ktl = 0; ktl < 4; ktl++) {
            const int kt = (half == 0) ? (4 + ktl) : ktl;
            // B fragments (frag-linear, conflict-free LDS.64)
            uint32_t bh[8][2], bl[8][2];
#pragma unroll
            for (int nt = 0; nt < 8; nt++) {
                uint2 vh = *(const uint2*)(sBhi + ((kt * 8 + nt) * 32 + lane) * 2);
                uint2 vl = *(const uint2*)(sBlo + ((kt * 8 + nt) * 32 + lane) * 2);
                bh[nt][0] = vh.x; bh[nt][1] = vh.y;
                bl[nt][0] = vl.x; bl[nt][1] = vl.y;
            }
            // A fragments from staged tile
            const int c0 = ktl * 8 + ft;
            uint32_t ah[2][4], al[2][4];
#pragma unroll
            for (int mt = 0; mt < 2; mt++) {
                int r0 = mt * 16 + fg;
                ah[mt][0] = awp[r0 * 33 + c0];
                ah[mt][1] = awp[(r0 + 8) * 33 + c0];
                ah[mt][2] = awp[r0 * 33 + c0 + 4];
                ah[mt][3] = awp[(r0 + 8) * 33 + c0 + 4];
                al[mt][0] = awp[1056 + r0 * 33 + c0];
                al[mt][1] = awp[1056 + (r0 + 8) * 33 + c0];
                al[mt][2] = awp[1056 + r0 * 33 + c0 + 4];
                al[mt][3] = awp[1056 + (r0 + 8) * 33 + c0 + 4];
            }
#pragma unroll
            for (int mt = 0; mt < 2; mt++)
#pragma unroll
                for (int nt = 0; nt < 8; nt++) {
                    mma16816(d[mt][nt], ah[mt], bh[nt]);
                    mma16816(d[mt][nt], ah[mt], bl[nt]);
                    mma16816(d[mt][nt], al[mt], bh[nt]);
                }
        }
    }

    // ---- stage D to smem (per-warp, stride 68) ----
    __syncwarp();
#pragma unroll
    for (int mt = 0; mt < 2; mt++)
#pragma unroll
        for (int nt = 0; nt < 8; nt++) {
            int r0 = mt * 16 + fg;
            float* p0 = (float*)(awp + r0 * 68 + nt * 8 + 2 * ft);
            float* p1 = (float*)(awp + (r0 + 8) * 68 + nt * 8 + 2 * ft);
            *(float2*)p0 = make_float2(d[mt][nt][0], d[mt][nt][1]);
            *(float2*)p1 = make_float2(d[mt][nt][2], d[mt][nt][3]);
        }
    __syncwarp();

    // ---- epilogue: h = D + c, relu, 64->2, log_softmax ----
    {
        const float* sc = smem + O_SC;
        const float2* sw2 = (const float2*)(smem + O_W2);
        float l0 = smem[O_SB2 + 0], l1 = smem[O_SB2 + 1];
        const float4* hrow = (const float4*)(awp + lane * 68);
#pragma unroll
        for (int c = 0; c < 16; c++) {
            float4 hv = hrow[c];
            float h0 = fmaxf(hv.x + sc[4 * c + 0], 0.0f);
            float h1 = fmaxf(hv.y + sc[4 * c + 1], 0.0f);
            float h2 = fmaxf(hv.z + sc[4 * c + 2], 0.0f);
            float h3 = fmaxf(hv.w + sc[4 * c + 3], 0.0f);
            float2 w0 = sw2[4 * c + 0], w1v = sw2[4 * c + 1];
            float2 w2v = sw2[4 * c + 2], w3v = sw2[4 * c + 3];
            l0 = fmaf(h0, w0.x, l0);
            l1 = fmaf(h0, w0.y, l1);
            l0 = fmaf(h1, w1v.x, l0);
            l1 = fmaf(h1, w1v.y, l1);
            l0 = fmaf(h2, w2v.x, l0);
            l1 = fmaf(h2, w2v.y, l1);
            l0 = fmaf(h3, w3v.x, l0);
            l1 = fmaf(h3, w3v.y, l1);
        }
        float mx = fmaxf(l0, l1);
        float lse = mx + log1pf(__expf(-fabsf(l0 - l1)));
        if (s < B) ((float2*)out)[s] = make_float2(l0 - lse, l1 - lse);
    }
}

extern "C" void kernel_launch(void* const* d_in, const int* in_sizes, int n_in,
                              void* d_out, int out_size) {
    const float* scene = (const float*)d_in[0];    // (B,8,16)
    const float* query = (const float*)d_in[1];    // (B,60)
    // d_in[2..7]: phases/freqs — unused (amplitude ODE is phase-free; delta/theta
    // amplitudes start at the fixed point 1.0 and stay there)
    const float* scene_w = (const float*)d_in[8];  // (16,64)
    const float* scene_b = (const float*)d_in[9];  // (64,)
    const float* query_w = (const float*)d_in[10]; // (60,64)
    const float* query_b = (const float*)d_in[11]; // (64,)
    const float* ro_w1 = (const float*)d_in[12];   // (152,64)
    const float* ro_b1 = (const float*)d_in[13];   // (64,)
    const float* ro_w2 = (const float*)d_in[14];   // (64,2)
    const float* ro_b2 = (const float*)d_in[15];   // (2,)
    float* out = (float*)d_out;

    int B = in_sizes[0] / 128;

    static bool attr_set = false;
    if (!attr_set) {
        cudaFuncSetAttribute(dtg_kernel, cudaFuncAttributeMaxDynamicSharedMemorySize,
                             SMEM_BYTES);
        attr_set = true;
    }

    prep1_kernel<<<18, 256>>>(query_w, query_b, ro_w1, ro_b1, scene_w);
    prep2_kernel<<<16, 256>>>(ro_w1);
    int grid = (B + 127) / 128;
    dtg_kernel<<<grid, 128, SMEM_BYTES>>>(scene, query, scene_b, ro_w2, ro_b2, out, B);
}